// round 10
// baseline (speedup 1.0000x reference)
#include <cuda_runtime.h>
#include <cstdint>
#include <cstddef>

typedef unsigned long long ull;

#define B_   32
#define T_   1024
#define C_   128
#define G_   896
#define H_   896
#define NTB  32768            /* T*B = columns of gx/hs */
#define BG   28672            /* B*G */
#define BTH  29360128         /* B*T*H */
#define NBLK 112
#define HST  898              /* padded h row stride (floats), even + mod32==2 */

// ---------------- static device scratch (no cudaMalloc anywhere) -----------
__device__ float d_gx[(size_t)2688 * NTB];   // [row r][t*32+b]
__device__ float d_hs[(size_t)G_ * NTB];     // [g][t*32+b]
__device__ float d_hbuf[2 * BG];             // ping-pong h, [j*32+b]
__device__ unsigned d_cnt;
__device__ unsigned d_gen;

// ---------------- packed fp32x2 helpers ------------------------------------
__device__ __forceinline__ void fma2(ull& d, ull a, ull b) {
    asm("fma.rn.f32x2 %0, %1, %2, %0;" : "+l"(d) : "l"(a), "l"(b));
}
__device__ __forceinline__ ull pack2(float x, float y) {
    ull r; asm("mov.b64 %0,{%1,%2};" : "=l"(r) : "f"(x), "f"(y)); return r;
}
__device__ __forceinline__ float2 unpack2(ull v) {
    float2 r; asm("mov.b64 {%0,%1},%2;" : "=f"(r.x), "=f"(r.y) : "l"(v)); return r;
}
union UF4 { float4 f4; ulonglong2 u2; };

// ---------------- GEMM: 128x128 tile, BK=8, 8x8 micro (4+4 split), FFMA2 ---
// MODE 0: d_gx[m][n] = sum_k w_ih[m][k] * x[b(n)][t(n)][k] + b_ih[m]
//         n = t*32 + b  (b = n&31, t = n>>5), K = 128
// MODE 1: out[b(n)][t(n)][m] = relu(sum_k w_post[m][k]*d_hs[k][n] + b_post[m]), K=896
template<int MODE>
__global__ void __launch_bounds__(256) gemm_k(
    const float* __restrict__ A, const float* __restrict__ Bsrc,
    const float* __restrict__ bias, float* __restrict__ Out, int K)
{
    __shared__ float As[8][132];
    __shared__ float Bs[8][132];
    const int tid = threadIdx.x;
    const int n0 = blockIdx.x * 128;
    const int m0 = blockIdx.y * 128;
    const int tn = tid & 15, tm = tid >> 4;
    const int ldn = tid >> 1, ldk = (tid & 1) * 4;
    const int ldk2 = tid >> 5, ldn2 = (tid & 31) * 4;

    const float* arow = A + (size_t)(m0 + ldn) * K + ldk;
    const float* bcol = nullptr;
    if (MODE == 0) {
        int n = n0 + ldn;
        bcol = Bsrc + ((size_t)(n & 31) * T_ + (n >> 5)) * C_ + ldk;
    }

    ull c2[8][4];
#pragma unroll
    for (int i = 0; i < 8; i++)
#pragma unroll
        for (int q = 0; q < 4; q++) c2[i][q] = 0ull;

    for (int kb = 0; kb < K; kb += 8) {
        float4 av = *(const float4*)(arow + kb);
        As[ldk+0][ldn]=av.x; As[ldk+1][ldn]=av.y;
        As[ldk+2][ldn]=av.z; As[ldk+3][ldn]=av.w;
        if (MODE == 0) {
            float4 bv = *(const float4*)(bcol + kb);
            Bs[ldk+0][ldn]=bv.x; Bs[ldk+1][ldn]=bv.y;
            Bs[ldk+2][ldn]=bv.z; Bs[ldk+3][ldn]=bv.w;
        } else {
            float4 bv = *(const float4*)(d_hs + (size_t)(kb + ldk2) * NTB + n0 + ldn2);
            *(float4*)&Bs[ldk2][ldn2] = bv;
        }
        __syncthreads();
#pragma unroll
        for (int k = 0; k < 8; k++) {
            float4 a0 = *(const float4*)&As[k][tm*4];
            float4 a1 = *(const float4*)&As[k][64 + tm*4];
            UF4 b0, b1;
            b0.f4 = *(const float4*)&Bs[k][tn*4];
            b1.f4 = *(const float4*)&Bs[k][64 + tn*4];
            float aa[8] = {a0.x,a0.y,a0.z,a0.w,a1.x,a1.y,a1.z,a1.w};
#pragma unroll
            for (int i = 0; i < 8; i++) {
                ull a2 = pack2(aa[i], aa[i]);
                fma2(c2[i][0], a2, b0.u2.x);
                fma2(c2[i][1], a2, b0.u2.y);
                fma2(c2[i][2], a2, b1.u2.x);
                fma2(c2[i][3], a2, b1.u2.y);
            }
        }
        __syncthreads();
    }

    float c[8][8];
#pragma unroll
    for (int i = 0; i < 8; i++)
#pragma unroll
        for (int q = 0; q < 4; q++) {
            float2 v = unpack2(c2[i][q]);
            c[i][2*q] = v.x; c[i][2*q+1] = v.y;
        }

    if (MODE == 0) {
#pragma unroll
        for (int i = 0; i < 8; i++) {
            int m = m0 + (i < 4 ? tm*4 + i : 64 + tm*4 + i - 4);
            float bi = bias[m];
            float* orow = Out + (size_t)m * NTB + n0;
            float4 lo = make_float4(c[i][0]+bi, c[i][1]+bi, c[i][2]+bi, c[i][3]+bi);
            float4 hi = make_float4(c[i][4]+bi, c[i][5]+bi, c[i][6]+bi, c[i][7]+bi);
            *(float4*)(orow + tn*4) = lo;
            *(float4*)(orow + 64 + tn*4) = hi;
        }
    } else {
        float bi[8];
#pragma unroll
        for (int i = 0; i < 8; i++)
            bi[i] = bias[m0 + (i < 4 ? tm*4 + i : 64 + tm*4 + i - 4)];
#pragma unroll
        for (int j = 0; j < 8; j++) {
            int n = n0 + (j < 4 ? tn*4 + j : 64 + tn*4 + j - 4);
            size_t base = ((size_t)(n & 31) * T_ + (n >> 5)) * H_ + m0;
            float4 lo, hi;
            lo.x = fmaxf(c[0][j]+bi[0], 0.f); lo.y = fmaxf(c[1][j]+bi[1], 0.f);
            lo.z = fmaxf(c[2][j]+bi[2], 0.f); lo.w = fmaxf(c[3][j]+bi[3], 0.f);
            hi.x = fmaxf(c[4][j]+bi[4], 0.f); hi.y = fmaxf(c[5][j]+bi[5], 0.f);
            hi.z = fmaxf(c[6][j]+bi[6], 0.f); hi.w = fmaxf(c[7][j]+bi[7], 0.f);
            *(float4*)(Out + base + tm*4) = lo;
            *(float4*)(Out + base + 64 + tm*4) = hi;
        }
    }
}

// ---------------- barrier state init (reset every launch -> deterministic) -
__global__ void init_k() { d_cnt = 0u; d_gen = 0u; }

// ---------------- persistent GRU scan --------------------------------------
// 112 CTAs x 128 threads. CTA owns 8 j (jbase..+7); warp w owns j0=jbase+2w, j0+1.
// lane = batch b. SMEM: h[32][898] + interleaved w_hh slice (24 rows).
__global__ void __launch_bounds__(128) scan_k(
    const float* __restrict__ h0, const float* __restrict__ w_hh,
    const float* __restrict__ b_hh, float* __restrict__ Out)
{
    extern __shared__ float sm[];
    float* h_s = sm;                  // 32*898 floats
    float* w_s = sm + 32*HST;         // 21504 floats
    const int tid = threadIdx.x;
    const int b = tid & 31;
    const int w = tid >> 5;
    const int jbase = blockIdx.x * 8;
    const int j0 = jbase + w*2;

    // w_hh slice -> interleaved SMEM: [warp][k/2][ (r,j0)(r,j1)(z,j0)(z,j1)(n,j0)(n,j1) x2 ]
    for (int e = tid; e < 21504; e += 128) {
        int jl = e / 2688, r2 = e - jl*2688;
        int gate = r2 / 896, k = r2 - gate*896;
        int ww = jl >> 1, jj = jl & 1;
        w_s[ww*5376 + (k>>1)*12 + (gate*2+jj)*2 + (k&1)] =
            w_hh[(size_t)(gate*896 + jbase + jl)*896 + k];
    }
    // initial h
    for (int e = tid; e < BG; e += 128) {
        int bb = e / 896, g = e - bb*896;
        h_s[bb*HST + g] = h0[e];
    }
    __syncthreads();

    const float bhr0 = b_hh[j0],      bhr1 = b_hh[j0+1];
    const float bhz0 = b_hh[896+j0],  bhz1 = b_hh[896+j0+1];
    const float bhn0 = b_hh[1792+j0], bhn1 = b_hh[1792+j0+1];
    const float* pr = d_gx + (size_t)j0*NTB + b;
    const float* pz = pr + (size_t)896*NTB;
    const float* pn = pr + (size_t)1792*NTB;
    const float* hrow = h_s + b*HST;
    const float4* wp = (const float4*)(w_s + w*5376);
    float* hsr = d_hs + (size_t)j0*NTB + b;

    for (int t = 0; t < T_; t++) {
        int tb = t*32;
        float xr0 = __ldcs(pr+tb), xr1 = __ldcs(pr+NTB+tb);
        float xz0 = __ldcs(pz+tb), xz1 = __ldcs(pz+NTB+tb);
        float xn0 = __ldcs(pn+tb), xn1 = __ldcs(pn+NTB+tb);

        ull ar0=0,ar1=0,az0=0,az1=0,an0=0,an1=0;
#pragma unroll 4
        for (int kk = 0; kk < 448; kk++) {
            ull h2 = *(const ull*)(hrow + 2*kk);
            UF4 w0,w1,w2;
            w0.f4 = wp[kk*3]; w1.f4 = wp[kk*3+1]; w2.f4 = wp[kk*3+2];
            fma2(ar0,h2,w0.u2.x); fma2(ar1,h2,w0.u2.y);
            fma2(az0,h2,w1.u2.x); fma2(az1,h2,w1.u2.y);
            fma2(an0,h2,w2.u2.x); fma2(an1,h2,w2.u2.y);
        }
        float2 v;
        v=unpack2(ar0); float gr0=v.x+v.y+bhr0;
        v=unpack2(ar1); float gr1=v.x+v.y+bhr1;
        v=unpack2(az0); float gz0=v.x+v.y+bhz0;
        v=unpack2(az1); float gz1=v.x+v.y+bhz1;
        v=unpack2(an0); float gn0=v.x+v.y+bhn0;
        v=unpack2(an1); float gn1=v.x+v.y+bhn1;

        float r0 = 1.f/(1.f+expf(-(xr0+gr0)));
        float r1 = 1.f/(1.f+expf(-(xr1+gr1)));
        float z0 = 1.f/(1.f+expf(-(xz0+gz0)));
        float z1 = 1.f/(1.f+expf(-(xz1+gz1)));
        float nn0 = tanhf(xn0 + r0*gn0);
        float nn1 = tanhf(xn1 + r1*gn1);
        float hp0 = hrow[j0], hp1 = hrow[j0+1];
        float h0n = (1.f - z0)*nn0 + z0*hp0;
        float h1n = (1.f - z1)*nn1 + z1*hp1;

        __stcg(hsr + tb, h0n);
        __stcg(hsr + NTB + tb, h1n);
        int nxt = (t+1) & 1;
        __stcg(d_hbuf + nxt*BG + j0*32 + b, h0n);
        __stcg(d_hbuf + nxt*BG + (j0+1)*32 + b, h1n);

        if (t == T_-1) {
            Out[(size_t)BTH + b*896 + j0]     = h0n;
            Out[(size_t)BTH + b*896 + j0 + 1] = h1n;
            break;
        }

        // -------- grid barrier (generation-based) --------
        __threadfence();
        __syncthreads();
        if (tid == 0) {
            unsigned a = atomicAdd(&d_cnt, 1u);
            if (a == (unsigned)gridDim.x - 1u) {
                d_cnt = 0u;
                __threadfence();
                atomicExch(&d_gen, (unsigned)(t+1));
            } else {
                while (*(volatile unsigned*)&d_gen < (unsigned)(t+1)) { }
            }
        }
        __syncthreads();

        // -------- reload full h into SMEM (L2 broadcast, bypass L1) --------
        const float4* hb4 = (const float4*)(d_hbuf + nxt*BG);
        for (int i4 = tid; i4 < 7168; i4 += 128) {
            int k = i4 >> 3, bq = (i4 & 7) << 2;
            float4 vv = __ldcg(hb4 + i4);
            float* p = h_s + bq*HST + k;
            p[0] = vv.x; p[HST] = vv.y; p[2*HST] = vv.z; p[3*HST] = vv.w;
        }
        __syncthreads();
    }
}

// ---------------- launch ----------------------------------------------------
extern "C" void kernel_launch(void* const* d_in, const int* in_sizes, int n_in,
                              void* d_out, int out_size) {
    (void)in_sizes; (void)n_in; (void)out_size;
    const float* x      = (const float*)d_in[0];
    const float* state  = (const float*)d_in[1];
    const float* w_ih   = (const float*)d_in[2];
    const float* w_hh   = (const float*)d_in[3];
    const float* b_ih   = (const float*)d_in[4];
    const float* b_hh   = (const float*)d_in[5];
    const float* w_post = (const float*)d_in[6];
    const float* b_post = (const float*)d_in[7];
    float* out = (float*)d_out;

    float* gx = nullptr;
    cudaGetSymbolAddress((void**)&gx, d_gx);

    static const int SMEM = (32*HST + 21504) * 4;   // 200,960 B
    cudaFuncSetAttribute(scan_k, cudaFuncAttributeMaxDynamicSharedMemorySize, SMEM);

    gemm_k<0><<<dim3(256, 21), 256>>>(w_ih, x, b_ih, gx, 128);
    init_k<<<1, 1>>>();
    scan_k<<<NBLK, 128, SMEM>>>(state, w_hh, b_hh, out);
    gemm_k<1><<<dim3(256, 7), 256>>>(w_post, nullptr, b_post, out, 896);
}

// round 11
// speedup vs baseline: 1.5631x; 1.5631x over previous
#include <cuda_runtime.h>
#include <cstdint>
#include <cstddef>

typedef unsigned long long ull;

#define B_   32
#define T_   1024
#define C_   128
#define G_   896
#define H_   896
#define NTB  32768            /* T*B = columns of gx/hs */
#define BG   28672            /* B*G */
#define BTH  29360128         /* B*T*H */
#define NBLK 112

// ---------------- static device scratch (no cudaMalloc anywhere) -----------
__device__ float d_gx[(size_t)2688 * NTB];   // [row r][t*32+b]
__device__ float d_hs[(size_t)G_ * NTB];     // [g][t*32+b]
__device__ float d_hbuf[2 * BG];             // ping-pong h, layout [kk][b][2]
__device__ unsigned d_flag[NBLK * 8];        // arrival flags, 32B-padded

// ---------------- packed fp32x2 helpers ------------------------------------
__device__ __forceinline__ void fma2(ull& d, ull a, ull b) {
    asm("fma.rn.f32x2 %0, %1, %2, %0;" : "+l"(d) : "l"(a), "l"(b));
}
__device__ __forceinline__ ull pack2(float x, float y) {
    ull r; asm("mov.b64 %0,{%1,%2};" : "=l"(r) : "f"(x), "f"(y)); return r;
}
__device__ __forceinline__ float2 unpack2(ull v) {
    float2 r; asm("mov.b64 {%0,%1},%2;" : "=f"(r.x), "=f"(r.y) : "l"(v)); return r;
}
union UF4 { float4 f4; ulonglong2 u2; };

// ---------------- GEMM: 128x128 tile, BK=8, 8x8 micro (4+4 split), FFMA2 ---
// MODE 0: d_gx[m][n] = sum_k w_ih[m][k] * x[b(n)][t(n)][k] + b_ih[m]
//         n = t*32 + b  (b = n&31, t = n>>5), K = 128
// MODE 1: out[b(n)][t(n)][m] = relu(sum_k w_post[m][k]*d_hs[k][n] + b_post[m]), K=896
template<int MODE>
__global__ void __launch_bounds__(256) gemm_k(
    const float* __restrict__ A, const float* __restrict__ Bsrc,
    const float* __restrict__ bias, float* __restrict__ Out, int K)
{
    __shared__ float As[8][132];
    __shared__ float Bs[8][132];
    const int tid = threadIdx.x;
    const int n0 = blockIdx.x * 128;
    const int m0 = blockIdx.y * 128;
    const int tn = tid & 15, tm = tid >> 4;
    const int ldn = tid >> 1, ldk = (tid & 1) * 4;
    const int ldk2 = tid >> 5, ldn2 = (tid & 31) * 4;

    const float* arow = A + (size_t)(m0 + ldn) * K + ldk;
    const float* bcol = nullptr;
    if (MODE == 0) {
        int n = n0 + ldn;
        bcol = Bsrc + ((size_t)(n & 31) * T_ + (n >> 5)) * C_ + ldk;
    }

    ull c2[8][4];
#pragma unroll
    for (int i = 0; i < 8; i++)
#pragma unroll
        for (int q = 0; q < 4; q++) c2[i][q] = 0ull;

    for (int kb = 0; kb < K; kb += 8) {
        float4 av = *(const float4*)(arow + kb);
        As[ldk+0][ldn]=av.x; As[ldk+1][ldn]=av.y;
        As[ldk+2][ldn]=av.z; As[ldk+3][ldn]=av.w;
        if (MODE == 0) {
            float4 bv = *(const float4*)(bcol + kb);
            Bs[ldk+0][ldn]=bv.x; Bs[ldk+1][ldn]=bv.y;
            Bs[ldk+2][ldn]=bv.z; Bs[ldk+3][ldn]=bv.w;
        } else {
            float4 bv = *(const float4*)(d_hs + (size_t)(kb + ldk2) * NTB + n0 + ldn2);
            *(float4*)&Bs[ldk2][ldn2] = bv;
        }
        __syncthreads();
#pragma unroll
        for (int k = 0; k < 8; k++) {
            float4 a0 = *(const float4*)&As[k][tm*4];
            float4 a1 = *(const float4*)&As[k][64 + tm*4];
            UF4 b0, b1;
            b0.f4 = *(const float4*)&Bs[k][tn*4];
            b1.f4 = *(const float4*)&Bs[k][64 + tn*4];
            float aa[8] = {a0.x,a0.y,a0.z,a0.w,a1.x,a1.y,a1.z,a1.w};
#pragma unroll
            for (int i = 0; i < 8; i++) {
                ull a2 = pack2(aa[i], aa[i]);
                fma2(c2[i][0], a2, b0.u2.x);
                fma2(c2[i][1], a2, b0.u2.y);
                fma2(c2[i][2], a2, b1.u2.x);
                fma2(c2[i][3], a2, b1.u2.y);
            }
        }
        __syncthreads();
    }

    float c[8][8];
#pragma unroll
    for (int i = 0; i < 8; i++)
#pragma unroll
        for (int q = 0; q < 4; q++) {
            float2 v = unpack2(c2[i][q]);
            c[i][2*q] = v.x; c[i][2*q+1] = v.y;
        }

    if (MODE == 0) {
#pragma unroll
        for (int i = 0; i < 8; i++) {
            int m = m0 + (i < 4 ? tm*4 + i : 64 + tm*4 + i - 4);
            float bi = bias[m];
            float* orow = Out + (size_t)m * NTB + n0;
            float4 lo = make_float4(c[i][0]+bi, c[i][1]+bi, c[i][2]+bi, c[i][3]+bi);
            float4 hi = make_float4(c[i][4]+bi, c[i][5]+bi, c[i][6]+bi, c[i][7]+bi);
            *(float4*)(orow + tn*4) = lo;
            *(float4*)(orow + 64 + tn*4) = hi;
        }
    } else {
        float bi[8];
#pragma unroll
        for (int i = 0; i < 8; i++)
            bi[i] = bias[m0 + (i < 4 ? tm*4 + i : 64 + tm*4 + i - 4)];
#pragma unroll
        for (int j = 0; j < 8; j++) {
            int n = n0 + (j < 4 ? tn*4 + j : 64 + tn*4 + j - 4);
            size_t base = ((size_t)(n & 31) * T_ + (n >> 5)) * H_ + m0;
            float4 lo, hi;
            lo.x = fmaxf(c[0][j]+bi[0], 0.f); lo.y = fmaxf(c[1][j]+bi[1], 0.f);
            lo.z = fmaxf(c[2][j]+bi[2], 0.f); lo.w = fmaxf(c[3][j]+bi[3], 0.f);
            hi.x = fmaxf(c[4][j]+bi[4], 0.f); hi.y = fmaxf(c[5][j]+bi[5], 0.f);
            hi.z = fmaxf(c[6][j]+bi[6], 0.f); hi.w = fmaxf(c[7][j]+bi[7], 0.f);
            *(float4*)(Out + base + tm*4) = lo;
            *(float4*)(Out + base + 64 + tm*4) = hi;
        }
    }
}

// ---------------- flag reset (every launch -> deterministic) ----------------
__global__ void init_k() {
    int t = threadIdx.x;
    if (t < NBLK) d_flag[t * 8] = 0u;
}

// ---------------- persistent GRU scan --------------------------------------
// 112 CTAs x 256 threads (8 warps). CTA owns 8 j (jbase..+7).
// All 8 warps cover the same 8-j octet; warp w handles k-pairs [w*56, w*56+56).
// lane = batch b. Per kk: 1 LDS.64 (h, lane-distinct) + 12 LDS.128 (w, bcast)
// + 24 FFMA2. Partial sums reduced via SMEM; thread (warp=jl, lane=b) finalizes
// gate j = jbase + jl for batch b.
// SMEM: h_s [448 kk][32 b][2] (28672 f) | w_s [448 kk][24 jg][2] (21504 f)
//       | red [8 w][24 jg][32 b] (6144 f)   total 225,280 B
__global__ void __launch_bounds__(256, 1) scan_k(
    const float* __restrict__ h0, const float* __restrict__ w_hh,
    const float* __restrict__ b_hh, float* __restrict__ Out)
{
    extern __shared__ float sm[];
    float* h_s = sm;                       // 28672
    float* w_s = sm + 28672;               // 21504
    float* red = sm + 28672 + 21504;       // 6144
    const int tid = threadIdx.x;
    const int b   = tid & 31;
    const int wi  = tid >> 5;              // warp id == jl for epilogue
    const int jbase = blockIdx.x * 8;
    const int j   = jbase + wi;

    // ---- load w_hh slice interleaved: w_s[kk*48 + jg*2 + p] = w_hh[gate*896+jbase+jl][2kk+p]
    for (int e = tid; e < 21504; e += 256) {
        int kk = e / 48, r = e - kk * 48;
        int jg = r >> 1, p = r & 1;
        int jl = jg / 3, gate = jg - jl * 3;
        w_s[e] = w_hh[(size_t)(gate * 896 + jbase + jl) * 896 + 2 * kk + p];
    }
    // ---- initial h into [kk][b][2] layout
    for (int e = tid; e < BG; e += 256) {
        int kk = e >> 6, r = e & 63;
        int bb = r >> 1, p = r & 1;
        h_s[e] = h0[bb * 896 + 2 * kk + p];
    }
    __syncthreads();

    const float bhr = b_hh[j], bhz = b_hh[896 + j], bhn = b_hh[1792 + j];
    const float* pr = d_gx + (size_t)j * NTB + b;
    const float* pz = pr + (size_t)896 * NTB;
    const float* pn = pr + (size_t)1792 * NTB;
    float* hsr = d_hs + (size_t)j * NTB + b;
    const int hoff = (j >> 1) * 64 + 2 * b + (j & 1);   // h element (j,b) in [kk][b][2]

    const ull* hp2 = (const ull*)h_s;       // hp2[kk*32 + b]
    const float4* wp4 = (const float4*)w_s; // wp4[kk*12 + q]
    const int kk0 = wi * 56;

    for (int t = 0; t < T_; t++) {
        const int tb = t * 32;
        // prefetch x-side gate activations (hide DRAM latency under the K loop)
        float xr = __ldcs(pr + tb);
        float xz = __ldcs(pz + tb);
        float xn = __ldcs(pn + tb);

        ull acc[24];
#pragma unroll
        for (int i = 0; i < 24; i++) acc[i] = 0ull;

        const ull* hptr = hp2 + (size_t)kk0 * 32 + b;
        const float4* wptr = wp4 + (size_t)kk0 * 12;
#pragma unroll 2
        for (int kk = 0; kk < 56; kk++) {
            ull h2 = hptr[kk * 32];
            const float4* wv = wptr + kk * 12;
#pragma unroll
            for (int q = 0; q < 12; q++) {
                UF4 wq; wq.f4 = wv[q];
                fma2(acc[2 * q],     h2, wq.u2.x);
                fma2(acc[2 * q + 1], h2, wq.u2.y);
            }
        }

        // ---- write partial sums (conflict-free: lanes differ in b)
#pragma unroll
        for (int jg = 0; jg < 24; jg++) {
            float2 v = unpack2(acc[jg]);
            red[wi * 768 + jg * 32 + b] = v.x + v.y;
        }
        __syncthreads();

        // ---- finalize gate j for batch b (thread (jl=wi, b))
        float gr = bhr, gz = bhz, gn = bhn;
#pragma unroll
        for (int w2 = 0; w2 < 8; w2++) {
            gr += red[w2 * 768 + (wi * 3 + 0) * 32 + b];
            gz += red[w2 * 768 + (wi * 3 + 1) * 32 + b];
            gn += red[w2 * 768 + (wi * 3 + 2) * 32 + b];
        }
        float r  = 1.f / (1.f + expf(-(xr + gr)));
        float z  = 1.f / (1.f + expf(-(xz + gz)));
        float nn = tanhf(xn + r * gn);
        float hp = h_s[hoff];
        float hn = (1.f - z) * nn + z * hp;

        __stcs(hsr + tb, hn);
        const int nxt = (t + 1) & 1;
        __stcg(d_hbuf + (size_t)nxt * BG + hoff, hn);

        if (t == T_ - 1) {
            Out[(size_t)BTH + b * 896 + j] = hn;
            break;
        }

        // ---- distributed-flag grid barrier -----------------------------
        __threadfence();
        __syncthreads();
        if (tid == 0)
            ((volatile unsigned*)d_flag)[blockIdx.x * 8] = (unsigned)(t + 1);
        if (tid < NBLK) {
            while (((volatile unsigned*)d_flag)[tid * 8] < (unsigned)(t + 1)) { }
        }
        __syncthreads();

        // ---- reload full h (straight copy, L2 broadcast, bypass L1) ----
        const float4* src = (const float4*)(d_hbuf + (size_t)nxt * BG);
        float4* dst = (float4*)h_s;
#pragma unroll 4
        for (int i = tid; i < 7168; i += 256)
            dst[i] = __ldcg(src + i);
        __syncthreads();
    }
}

// ---------------- launch ----------------------------------------------------
extern "C" void kernel_launch(void* const* d_in, const int* in_sizes, int n_in,
                              void* d_out, int out_size) {
    (void)in_sizes; (void)n_in; (void)out_size;
    const float* x      = (const float*)d_in[0];
    const float* state  = (const float*)d_in[1];
    const float* w_ih   = (const float*)d_in[2];
    const float* w_hh   = (const float*)d_in[3];
    const float* b_ih   = (const float*)d_in[4];
    const float* b_hh   = (const float*)d_in[5];
    const float* w_post = (const float*)d_in[6];
    const float* b_post = (const float*)d_in[7];
    float* out = (float*)d_out;

    float* gx = nullptr;
    cudaGetSymbolAddress((void**)&gx, d_gx);

    static const int SMEM = (28672 + 21504 + 6144) * 4;   // 225,280 B
    cudaFuncSetAttribute(scan_k, cudaFuncAttributeMaxDynamicSharedMemorySize, SMEM);

    gemm_k<0><<<dim3(256, 21), 256>>>(w_ih, x, b_ih, gx, 128);
    init_k<<<1, 128>>>();
    scan_k<<<NBLK, 256, SMEM>>>(state, w_hh, b_hh, out);
    gemm_k<1><<<dim3(256, 7), 256>>>(w_post, nullptr, b_post, out, 896);
}

// round 12
// speedup vs baseline: 1.5731x; 1.0064x over previous
#include <cuda_runtime.h>
#include <cstdint>
#include <cstddef>

typedef unsigned long long ull;

#define B_   32
#define T_   1024
#define C_   128
#define G_   896
#define H_   896
#define NTB  32768            /* T*B = columns of gx/hs */
#define BG   28672            /* B*G */
#define BTH  29360128         /* B*T*H */
#define NBLK 112

// ---------------- static device scratch (no cudaMalloc anywhere) -----------
__device__ float d_gx[(size_t)2688 * NTB];   // [row r][t*32+b]
__device__ float d_hs[(size_t)G_ * NTB];     // [g][t*32+b]
__device__ float d_hbuf[2 * BG];             // ping-pong h, layout [kk][b][2]
__device__ unsigned d_flag[NBLK * 8];        // arrival flags, 32B-padded

// ---------------- packed fp32x2 helpers ------------------------------------
__device__ __forceinline__ void fma2(ull& d, ull a, ull b) {
    asm("fma.rn.f32x2 %0, %1, %2, %0;" : "+l"(d) : "l"(a), "l"(b));
}
__device__ __forceinline__ ull pack2(float x, float y) {
    ull r; asm("mov.b64 %0,{%1,%2};" : "=l"(r) : "f"(x), "f"(y)); return r;
}
__device__ __forceinline__ float2 unpack2(ull v) {
    float2 r; asm("mov.b64 {%0,%1},%2;" : "=f"(r.x), "=f"(r.y) : "l"(v)); return r;
}
union UF4 { float4 f4; ulonglong2 u2; };

// ---------------- GEMM: 128x128 tile, BK=8, 8x8 micro (4+4 split), FFMA2 ---
// MODE 0: d_gx[m][n] = sum_k w_ih[m][k] * x[b(n)][t(n)][k] + b_ih[m]
//         n = t*32 + b  (b = n&31, t = n>>5), K = 128
// MODE 1: out[b(n)][t(n)][m] = relu(sum_k w_post[m][k]*d_hs[k][n] + b_post[m]), K=896
template<int MODE>
__global__ void __launch_bounds__(256) gemm_k(
    const float* __restrict__ A, const float* __restrict__ Bsrc,
    const float* __restrict__ bias, float* __restrict__ Out, int K)
{
    __shared__ float As[8][132];
    __shared__ float Bs[8][132];
    const int tid = threadIdx.x;
    const int n0 = blockIdx.x * 128;
    const int m0 = blockIdx.y * 128;
    const int tn = tid & 15, tm = tid >> 4;
    const int ldn = tid >> 1, ldk = (tid & 1) * 4;
    const int ldk2 = tid >> 5, ldn2 = (tid & 31) * 4;

    const float* arow = A + (size_t)(m0 + ldn) * K + ldk;
    const float* bcol = nullptr;
    if (MODE == 0) {
        int n = n0 + ldn;
        bcol = Bsrc + ((size_t)(n & 31) * T_ + (n >> 5)) * C_ + ldk;
    }

    ull c2[8][4];
#pragma unroll
    for (int i = 0; i < 8; i++)
#pragma unroll
        for (int q = 0; q < 4; q++) c2[i][q] = 0ull;

    for (int kb = 0; kb < K; kb += 8) {
        float4 av = *(const float4*)(arow + kb);
        As[ldk+0][ldn]=av.x; As[ldk+1][ldn]=av.y;
        As[ldk+2][ldn]=av.z; As[ldk+3][ldn]=av.w;
        if (MODE == 0) {
            float4 bv = *(const float4*)(bcol + kb);
            Bs[ldk+0][ldn]=bv.x; Bs[ldk+1][ldn]=bv.y;
            Bs[ldk+2][ldn]=bv.z; Bs[ldk+3][ldn]=bv.w;
        } else {
            float4 bv = *(const float4*)(d_hs + (size_t)(kb + ldk2) * NTB + n0 + ldn2);
            *(float4*)&Bs[ldk2][ldn2] = bv;
        }
        __syncthreads();
#pragma unroll
        for (int k = 0; k < 8; k++) {
            float4 a0 = *(const float4*)&As[k][tm*4];
            float4 a1 = *(const float4*)&As[k][64 + tm*4];
            UF4 b0, b1;
            b0.f4 = *(const float4*)&Bs[k][tn*4];
            b1.f4 = *(const float4*)&Bs[k][64 + tn*4];
            float aa[8] = {a0.x,a0.y,a0.z,a0.w,a1.x,a1.y,a1.z,a1.w};
#pragma unroll
            for (int i = 0; i < 8; i++) {
                ull a2 = pack2(aa[i], aa[i]);
                fma2(c2[i][0], a2, b0.u2.x);
                fma2(c2[i][1], a2, b0.u2.y);
                fma2(c2[i][2], a2, b1.u2.x);
                fma2(c2[i][3], a2, b1.u2.y);
            }
        }
        __syncthreads();
    }

    float c[8][8];
#pragma unroll
    for (int i = 0; i < 8; i++)
#pragma unroll
        for (int q = 0; q < 4; q++) {
            float2 v = unpack2(c2[i][q]);
            c[i][2*q] = v.x; c[i][2*q+1] = v.y;
        }

    if (MODE == 0) {
#pragma unroll
        for (int i = 0; i < 8; i++) {
            int m = m0 + (i < 4 ? tm*4 + i : 64 + tm*4 + i - 4);
            float bi = bias[m];
            float* orow = Out + (size_t)m * NTB + n0;
            float4 lo = make_float4(c[i][0]+bi, c[i][1]+bi, c[i][2]+bi, c[i][3]+bi);
            float4 hi = make_float4(c[i][4]+bi, c[i][5]+bi, c[i][6]+bi, c[i][7]+bi);
            *(float4*)(orow + tn*4) = lo;
            *(float4*)(orow + 64 + tn*4) = hi;
        }
    } else {
        float bi[8];
#pragma unroll
        for (int i = 0; i < 8; i++)
            bi[i] = bias[m0 + (i < 4 ? tm*4 + i : 64 + tm*4 + i - 4)];
#pragma unroll
        for (int j = 0; j < 8; j++) {
            int n = n0 + (j < 4 ? tn*4 + j : 64 + tn*4 + j - 4);
            size_t base = ((size_t)(n & 31) * T_ + (n >> 5)) * H_ + m0;
            float4 lo, hi;
            lo.x = fmaxf(c[0][j]+bi[0], 0.f); lo.y = fmaxf(c[1][j]+bi[1], 0.f);
            lo.z = fmaxf(c[2][j]+bi[2], 0.f); lo.w = fmaxf(c[3][j]+bi[3], 0.f);
            hi.x = fmaxf(c[4][j]+bi[4], 0.f); hi.y = fmaxf(c[5][j]+bi[5], 0.f);
            hi.z = fmaxf(c[6][j]+bi[6], 0.f); hi.w = fmaxf(c[7][j]+bi[7], 0.f);
            *(float4*)(Out + base + tm*4) = lo;
            *(float4*)(Out + base + 64 + tm*4) = hi;
        }
    }
}

// ---------------- flag reset (every launch -> deterministic) ----------------
__global__ void init_k() {
    int t = threadIdx.x;
    if (t < NBLK) d_flag[t * 8] = 0u;
}

// ---------------- persistent GRU scan --------------------------------------
// 112 CTAs x 256 threads (8 warps). CTA owns 8 j (jbase..+7).
// All 8 warps cover the same 8-j octet; warp w handles k-pairs [w*56, w*56+56).
// lane = batch b. Inner loop software-pipelined: per kk, weights split into
// two 6-wide ulonglong2 register buffers with one-stage lookahead; h2
// prefetched one kk ahead. Every LDS has >=24 cyc of work before first use.
// SMEM: h_s [448 kk][32 b][2] + 64 pad (28736 f) | w_s [448 kk][24 jg][2]
//       (21504 f) | red [8 w][24 jg][32 b] (6144 f)   total 225,536 B
__global__ void __launch_bounds__(256, 1) scan_k(
    const float* __restrict__ h0, const float* __restrict__ w_hh,
    const float* __restrict__ b_hh, float* __restrict__ Out)
{
    extern __shared__ float sm[];
    float* h_s = sm;                       // 28736 (28672 + 64 pad)
    float* w_s = sm + 28736;               // 21504
    float* red = sm + 28736 + 21504;       // 6144
    const int tid = threadIdx.x;
    const int b   = tid & 31;
    const int wi  = tid >> 5;              // warp id == jl for epilogue
    const int jbase = blockIdx.x * 8;
    const int j   = jbase + wi;

    // ---- load w_hh slice interleaved: w_s[kk*48 + jg*2 + p] = w_hh[gate*896+jbase+jl][2kk+p]
    for (int e = tid; e < 21504; e += 256) {
        int kk = e / 48, r = e - kk * 48;
        int jg = r >> 1, p = r & 1;
        int jl = jg / 3, gate = jg - jl * 3;
        w_s[e] = w_hh[(size_t)(gate * 896 + jbase + jl) * 896 + 2 * kk + p];
    }
    // ---- initial h into [kk][b][2] layout
    for (int e = tid; e < BG; e += 256) {
        int kk = e >> 6, r = e & 63;
        int bb = r >> 1, p = r & 1;
        h_s[e] = h0[bb * 896 + 2 * kk + p];
    }
    __syncthreads();

    const float bhr = b_hh[j], bhz = b_hh[896 + j], bhn = b_hh[1792 + j];
    const float* pr = d_gx + (size_t)j * NTB + b;
    const float* pz = pr + (size_t)896 * NTB;
    const float* pn = pr + (size_t)1792 * NTB;
    float* hsr = d_hs + (size_t)j * NTB + b;
    const int hoff = (j >> 1) * 64 + 2 * b + (j & 1);   // h element (j,b) in [kk][b][2]

    const int kk0 = wi * 56;
    const ull* hptr = (const ull*)h_s + (size_t)kk0 * 32 + b;
    const ulonglong2* wv = (const ulonglong2*)w_s + (size_t)kk0 * 12;

    for (int t = 0; t < T_; t++) {
        const int tb = t * 32;
        // prefetch x-side gate activations (DRAM latency hidden under K loop)
        float xr = __ldcs(pr + tb);
        float xz = __ldcs(pz + tb);
        float xn = __ldcs(pn + tb);

        ull acc[24];
#pragma unroll
        for (int i = 0; i < 24; i++) acc[i] = 0ull;

        // ---- software-pipelined K loop ----
        ulonglong2 wa[6], wb[6];
#pragma unroll
        for (int q = 0; q < 6; q++) wa[q] = wv[q];
        ull h2 = hptr[0];

#pragma unroll 2
        for (int kk = 0; kk < 56; kk++) {
            const ulonglong2* wk = wv + kk * 12;
            ull h2c = h2;
#pragma unroll
            for (int q = 0; q < 6; q++) wb[q] = wk[6 + q];
            h2 = hptr[(kk + 1) * 32];          // pad makes kk=55 read safe
#pragma unroll
            for (int q = 0; q < 6; q++) {
                fma2(acc[2 * q],     h2c, wa[q].x);
                fma2(acc[2 * q + 1], h2c, wa[q].y);
            }
#pragma unroll
            for (int q = 0; q < 6; q++) wa[q] = wk[12 + q];   // next kk, first half
#pragma unroll
            for (int q = 0; q < 6; q++) {
                fma2(acc[12 + 2 * q],     h2c, wb[q].x);
                fma2(acc[12 + 2 * q + 1], h2c, wb[q].y);
            }
        }

        // ---- write partial sums (conflict-free: lanes differ in b)
#pragma unroll
        for (int jg = 0; jg < 24; jg++) {
            float2 v = unpack2(acc[jg]);
            red[wi * 768 + jg * 32 + b] = v.x + v.y;
        }
        __syncthreads();

        // ---- finalize gate j for batch b (thread (jl=wi, b))
        float gr = bhr, gz = bhz, gn = bhn;
#pragma unroll
        for (int w2 = 0; w2 < 8; w2++) {
            gr += red[w2 * 768 + (wi * 3 + 0) * 32 + b];
            gz += red[w2 * 768 + (wi * 3 + 1) * 32 + b];
            gn += red[w2 * 768 + (wi * 3 + 2) * 32 + b];
        }
        float r  = 1.f / (1.f + expf(-(xr + gr)));
        float z  = 1.f / (1.f + expf(-(xz + gz)));
        float nn = tanhf(xn + r * gn);
        float hp = h_s[hoff];
        float hn = (1.f - z) * nn + z * hp;

        const int nxt = (t + 1) & 1;
        __stcg(d_hbuf + (size_t)nxt * BG + hoff, hn);   // peers need this

        if (t == T_ - 1) {
            __stcs(hsr + tb, hn);
            Out[(size_t)BTH + b * 896 + j] = hn;
            break;
        }

        // ---- distributed-flag grid barrier -----------------------------
        __threadfence();
        __syncthreads();
        if (tid == 0)
            ((volatile unsigned*)d_flag)[blockIdx.x * 8] = (unsigned)(t + 1);
        __stcs(hsr + tb, hn);                 // only post-GEMM needs it: spin window
        if (tid < NBLK) {
            while (((volatile unsigned*)d_flag)[tid * 8] < (unsigned)(t + 1)) { }
        }
        __syncthreads();

        // ---- reload full h (straight copy, L2 broadcast, bypass L1) ----
        const float4* src = (const float4*)(d_hbuf + (size_t)nxt * BG);
        float4* dst = (float4*)h_s;
#pragma unroll 4
        for (int i = tid; i < 7168; i += 256)
            dst[i] = __ldcg(src + i);
        __syncthreads();
    }
}

// ---------------- launch ----------------------------------------------------
extern "C" void kernel_launch(void* const* d_in, const int* in_sizes, int n_in,
                              void* d_out, int out_size) {
    (void)in_sizes; (void)n_in; (void)out_size;
    const float* x      = (const float*)d_in[0];
    const float* state  = (const float*)d_in[1];
    const float* w_ih   = (const float*)d_in[2];
    const float* w_hh   = (const float*)d_in[3];
    const float* b_ih   = (const float*)d_in[4];
    const float* b_hh   = (const float*)d_in[5];
    const float* w_post = (const float*)d_in[6];
    const float* b_post = (const float*)d_in[7];
    float* out = (float*)d_out;

    float* gx = nullptr;
    cudaGetSymbolAddress((void**)&gx, d_gx);

    static const int SMEM = (28736 + 21504 + 6144) * 4;   // 225,536 B
    cudaFuncSetAttribute(scan_k, cudaFuncAttributeMaxDynamicSharedMemorySize, SMEM);

    gemm_k<0><<<dim3(256, 21), 256>>>(w_ih, x, b_ih, gx, 128);
    init_k<<<1, 128>>>();
    scan_k<<<NBLK, 256, SMEM>>>(state, w_hh, b_hh, out);
    gemm_k<1><<<dim3(256, 7), 256>>>(w_post, nullptr, b_post, out, 896);
}

// round 13
// speedup vs baseline: 1.5803x; 1.0045x over previous
#include <cuda_runtime.h>
#include <cstdint>
#include <cstddef>

typedef unsigned long long ull;

#define B_   32
#define T_   1024
#define C_   128
#define G_   896
#define H_   896
#define NTB  32768            /* T*B = columns of gx/hs */
#define BG   28672            /* B*G */
#define BTH  29360128         /* B*T*H */
#define NBLK 112

// ---------------- static device scratch (no cudaMalloc anywhere) -----------
__device__ float d_gx[(size_t)2688 * NTB];   // [row r][t*32+b]
__device__ float d_hs[(size_t)G_ * NTB];     // [g][t*32+b]
__device__ float d_hbuf[2 * BG];             // ping-pong h, layout [kk][b][2]
__device__ unsigned d_flag[NBLK * 8];        // arrival flags, 32B-padded

// ---------------- packed fp32x2 helpers ------------------------------------
__device__ __forceinline__ void fma2(ull& d, ull a, ull b) {
    asm("fma.rn.f32x2 %0, %1, %2, %0;" : "+l"(d) : "l"(a), "l"(b));
}
__device__ __forceinline__ ull pack2(float x, float y) {
    ull r; asm("mov.b64 %0,{%1,%2};" : "=l"(r) : "f"(x), "f"(y)); return r;
}
__device__ __forceinline__ float2 unpack2(ull v) {
    float2 r; asm("mov.b64 {%0,%1},%2;" : "=f"(r.x), "=f"(r.y) : "l"(v)); return r;
}
union UF4 { float4 f4; ulonglong2 u2; };

// ---------------- GEMM: 128x128 tile, BK=8, 8x8 micro (4+4 split), FFMA2 ---
// MODE 0: d_gx[m][n] = sum_k w_ih[m][k] * x[b(n)][t(n)][k] + b_ih[m]
//         n = t*32 + b  (b = n&31, t = n>>5), K = 128
// MODE 1: out[b(n)][t(n)][m] = relu(sum_k w_post[m][k]*d_hs[k][n] + b_post[m]), K=896
template<int MODE>
__global__ void __launch_bounds__(256) gemm_k(
    const float* __restrict__ A, const float* __restrict__ Bsrc,
    const float* __restrict__ bias, float* __restrict__ Out, int K)
{
    __shared__ float As[8][132];
    __shared__ float Bs[8][132];
    const int tid = threadIdx.x;
    const int n0 = blockIdx.x * 128;
    const int m0 = blockIdx.y * 128;
    const int tn = tid & 15, tm = tid >> 4;
    const int ldn = tid >> 1, ldk = (tid & 1) * 4;
    const int ldk2 = tid >> 5, ldn2 = (tid & 31) * 4;

    const float* arow = A + (size_t)(m0 + ldn) * K + ldk;
    const float* bcol = nullptr;
    if (MODE == 0) {
        int n = n0 + ldn;
        bcol = Bsrc + ((size_t)(n & 31) * T_ + (n >> 5)) * C_ + ldk;
    }

    ull c2[8][4];
#pragma unroll
    for (int i = 0; i < 8; i++)
#pragma unroll
        for (int q = 0; q < 4; q++) c2[i][q] = 0ull;

    for (int kb = 0; kb < K; kb += 8) {
        float4 av = *(const float4*)(arow + kb);
        As[ldk+0][ldn]=av.x; As[ldk+1][ldn]=av.y;
        As[ldk+2][ldn]=av.z; As[ldk+3][ldn]=av.w;
        if (MODE == 0) {
            float4 bv = *(const float4*)(bcol + kb);
            Bs[ldk+0][ldn]=bv.x; Bs[ldk+1][ldn]=bv.y;
            Bs[ldk+2][ldn]=bv.z; Bs[ldk+3][ldn]=bv.w;
        } else {
            float4 bv = *(const float4*)(d_hs + (size_t)(kb + ldk2) * NTB + n0 + ldn2);
            *(float4*)&Bs[ldk2][ldn2] = bv;
        }
        __syncthreads();
#pragma unroll
        for (int k = 0; k < 8; k++) {
            float4 a0 = *(const float4*)&As[k][tm*4];
            float4 a1 = *(const float4*)&As[k][64 + tm*4];
            UF4 b0, b1;
            b0.f4 = *(const float4*)&Bs[k][tn*4];
            b1.f4 = *(const float4*)&Bs[k][64 + tn*4];
            float aa[8] = {a0.x,a0.y,a0.z,a0.w,a1.x,a1.y,a1.z,a1.w};
#pragma unroll
            for (int i = 0; i < 8; i++) {
                ull a2 = pack2(aa[i], aa[i]);
                fma2(c2[i][0], a2, b0.u2.x);
                fma2(c2[i][1], a2, b0.u2.y);
                fma2(c2[i][2], a2, b1.u2.x);
                fma2(c2[i][3], a2, b1.u2.y);
            }
        }
        __syncthreads();
    }

    float c[8][8];
#pragma unroll
    for (int i = 0; i < 8; i++)
#pragma unroll
        for (int q = 0; q < 4; q++) {
            float2 v = unpack2(c2[i][q]);
            c[i][2*q] = v.x; c[i][2*q+1] = v.y;
        }

    if (MODE == 0) {
#pragma unroll
        for (int i = 0; i < 8; i++) {
            int m = m0 + (i < 4 ? tm*4 + i : 64 + tm*4 + i - 4);
            float bi = bias[m];
            float* orow = Out + (size_t)m * NTB + n0;
            float4 lo = make_float4(c[i][0]+bi, c[i][1]+bi, c[i][2]+bi, c[i][3]+bi);
            float4 hi = make_float4(c[i][4]+bi, c[i][5]+bi, c[i][6]+bi, c[i][7]+bi);
            *(float4*)(orow + tn*4) = lo;
            *(float4*)(orow + 64 + tn*4) = hi;
        }
    } else {
        float bi[8];
#pragma unroll
        for (int i = 0; i < 8; i++)
            bi[i] = bias[m0 + (i < 4 ? tm*4 + i : 64 + tm*4 + i - 4)];
#pragma unroll
        for (int j = 0; j < 8; j++) {
            int n = n0 + (j < 4 ? tn*4 + j : 64 + tn*4 + j - 4);
            size_t base = ((size_t)(n & 31) * T_ + (n >> 5)) * H_ + m0;
            float4 lo, hi;
            lo.x = fmaxf(c[0][j]+bi[0], 0.f); lo.y = fmaxf(c[1][j]+bi[1], 0.f);
            lo.z = fmaxf(c[2][j]+bi[2], 0.f); lo.w = fmaxf(c[3][j]+bi[3], 0.f);
            hi.x = fmaxf(c[4][j]+bi[4], 0.f); hi.y = fmaxf(c[5][j]+bi[5], 0.f);
            hi.z = fmaxf(c[6][j]+bi[6], 0.f); hi.w = fmaxf(c[7][j]+bi[7], 0.f);
            *(float4*)(Out + base + tm*4) = lo;
            *(float4*)(Out + base + 64 + tm*4) = hi;
        }
    }
}

// ---------------- flag reset (every launch -> deterministic) ----------------
__global__ void init_k() {
    int t = threadIdx.x;
    if (t < NBLK) d_flag[t * 8] = 0u;
}

// ---------------- persistent GRU scan --------------------------------------
// 112 CTAs x 256 threads (8 warps). CTA owns 8 j (jbase..+7).
// All 8 warps cover the same 8-j octet; warp w handles k-pairs [w*56, w*56+56).
// lane = batch b. Inner loop software-pipelined: per kk, weights split into
// two 6-wide ulonglong2 register buffers with one-stage lookahead; h2
// prefetched one kk ahead. Every LDS has >=24 cyc of work before first use.
// SMEM: h_s [448 kk][32 b][2] + 64 pad (28736 f) | w_s [448 kk][24 jg][2]
//       (21504 f) | red [8 w][24 jg][32 b] (6144 f)   total 225,536 B
__global__ void __launch_bounds__(256, 1) scan_k(
    const float* __restrict__ h0, const float* __restrict__ w_hh,
    const float* __restrict__ b_hh, float* __restrict__ Out)
{
    extern __shared__ float sm[];
    float* h_s = sm;                       // 28736 (28672 + 64 pad)
    float* w_s = sm + 28736;               // 21504
    float* red = sm + 28736 + 21504;       // 6144
    const int tid = threadIdx.x;
    const int b   = tid & 31;
    const int wi  = tid >> 5;              // warp id == jl for epilogue
    const int jbase = blockIdx.x * 8;
    const int j   = jbase + wi;

    // ---- load w_hh slice interleaved: w_s[kk*48 + jg*2 + p] = w_hh[gate*896+jbase+jl][2kk+p]
    for (int e = tid; e < 21504; e += 256) {
        int kk = e / 48, r = e - kk * 48;
        int jg = r >> 1, p = r & 1;
        int jl = jg / 3, gate = jg - jl * 3;
        w_s[e] = w_hh[(size_t)(gate * 896 + jbase + jl) * 896 + 2 * kk + p];
    }
    // ---- initial h into [kk][b][2] layout
    for (int e = tid; e < BG; e += 256) {
        int kk = e >> 6, r = e & 63;
        int bb = r >> 1, p = r & 1;
        h_s[e] = h0[bb * 896 + 2 * kk + p];
    }
    __syncthreads();

    const float bhr = b_hh[j], bhz = b_hh[896 + j], bhn = b_hh[1792 + j];
    const float* pr = d_gx + (size_t)j * NTB + b;
    const float* pz = pr + (size_t)896 * NTB;
    const float* pn = pr + (size_t)1792 * NTB;
    float* hsr = d_hs + (size_t)j * NTB + b;
    const int hoff = (j >> 1) * 64 + 2 * b + (j & 1);   // h element (j,b) in [kk][b][2]

    const int kk0 = wi * 56;
    const ull* hptr = (const ull*)h_s + (size_t)kk0 * 32 + b;
    const ulonglong2* wv = (const ulonglong2*)w_s + (size_t)kk0 * 12;

    for (int t = 0; t < T_; t++) {
        const int tb = t * 32;
        // prefetch x-side gate activations (DRAM latency hidden under K loop)
        float xr = __ldcs(pr + tb);
        float xz = __ldcs(pz + tb);
        float xn = __ldcs(pn + tb);

        ull acc[24];
#pragma unroll
        for (int i = 0; i < 24; i++) acc[i] = 0ull;

        // ---- software-pipelined K loop ----
        ulonglong2 wa[6], wb[6];
#pragma unroll
        for (int q = 0; q < 6; q++) wa[q] = wv[q];
        ull h2 = hptr[0];

#pragma unroll 2
        for (int kk = 0; kk < 56; kk++) {
            const ulonglong2* wk = wv + kk * 12;
            ull h2c = h2;
#pragma unroll
            for (int q = 0; q < 6; q++) wb[q] = wk[6 + q];
            h2 = hptr[(kk + 1) * 32];          // pad makes kk=55 read safe
#pragma unroll
            for (int q = 0; q < 6; q++) {
                fma2(acc[2 * q],     h2c, wa[q].x);
                fma2(acc[2 * q + 1], h2c, wa[q].y);
            }
#pragma unroll
            for (int q = 0; q < 6; q++) wa[q] = wk[12 + q];   // next kk, first half
#pragma unroll
            for (int q = 0; q < 6; q++) {
                fma2(acc[12 + 2 * q],     h2c, wb[q].x);
                fma2(acc[12 + 2 * q + 1], h2c, wb[q].y);
            }
        }

        // ---- write partial sums (conflict-free: lanes differ in b)
#pragma unroll
        for (int jg = 0; jg < 24; jg++) {
            float2 v = unpack2(acc[jg]);
            red[wi * 768 + jg * 32 + b] = v.x + v.y;
        }
        __syncthreads();

        // ---- finalize gate j for batch b (thread (jl=wi, b))
        float gr = bhr, gz = bhz, gn = bhn;
#pragma unroll
        for (int w2 = 0; w2 < 8; w2++) {
            gr += red[w2 * 768 + (wi * 3 + 0) * 32 + b];
            gz += red[w2 * 768 + (wi * 3 + 1) * 32 + b];
            gn += red[w2 * 768 + (wi * 3 + 2) * 32 + b];
        }
        float r  = 1.f / (1.f + expf(-(xr + gr)));
        float z  = 1.f / (1.f + expf(-(xz + gz)));
        float nn = tanhf(xn + r * gn);
        float hp = h_s[hoff];
        float hn = (1.f - z) * nn + z * hp;

        const int nxt = (t + 1) & 1;
        __stcg(d_hbuf + (size_t)nxt * BG + hoff, hn);   // peers need this

        if (t == T_ - 1) {
            __stcs(hsr + tb, hn);
            Out[(size_t)BTH + b * 896 + j] = hn;
            break;
        }

        // ---- distributed-flag grid barrier -----------------------------
        __threadfence();
        __syncthreads();
        if (tid == 0)
            ((volatile unsigned*)d_flag)[blockIdx.x * 8] = (unsigned)(t + 1);
        __stcs(hsr + tb, hn);                 // only post-GEMM needs it: spin window
        if (tid < NBLK) {
            while (((volatile unsigned*)d_flag)[tid * 8] < (unsigned)(t + 1)) { }
        }
        __syncthreads();

        // ---- reload full h (straight copy, L2 broadcast, bypass L1) ----
        const float4* src = (const float4*)(d_hbuf + (size_t)nxt * BG);
        float4* dst = (float4*)h_s;
#pragma unroll 4
        for (int i = tid; i < 7168; i += 256)
            dst[i] = __ldcg(src + i);
        __syncthreads();
    }
}

// ---------------- launch ----------------------------------------------------
extern "C" void kernel_launch(void* const* d_in, const int* in_sizes, int n_in,
                              void* d_out, int out_size) {
    (void)in_sizes; (void)n_in; (void)out_size;
    const float* x      = (const float*)d_in[0];
    const float* state  = (const float*)d_in[1];
    const float* w_ih   = (const float*)d_in[2];
    const float* w_hh   = (const float*)d_in[3];
    const float* b_ih   = (const float*)d_in[4];
    const float* b_hh   = (const float*)d_in[5];
    const float* w_post = (const float*)d_in[6];
    const float* b_post = (const float*)d_in[7];
    float* out = (float*)d_out;

    float* gx = nullptr;
    cudaGetSymbolAddress((void**)&gx, d_gx);

    static const int SMEM = (28736 + 21504 + 6144) * 4;   // 225,536 B
    cudaFuncSetAttribute(scan_k, cudaFuncAttributeMaxDynamicSharedMemorySize, SMEM);

    gemm_k<0><<<dim3(256, 21), 256>>>(w_ih, x, b_ih, gx, 128);
    init_k<<<1, 128>>>();
    scan_k<<<NBLK, 256, SMEM>>>(state, w_hh, b_hh, out);
    gemm_k<1><<<dim3(256, 7), 256>>>(w_post, nullptr, b_post, out, 896);
}

// round 15
// speedup vs baseline: 1.6420x; 1.0391x over previous
#include <cuda_runtime.h>
#include <cuda_fp16.h>
#include <cstdint>
#include <cstddef>

typedef unsigned long long ull;

#define B_   32
#define T_   1024
#define C_   128
#define G_   896
#define H_   896
#define NTB  32768
#define BG   28672
#define BTH  29360128
#define ASTR 456              /* padded fp16 row stride (halves) */

// ---------------- static device scratch ------------------------------------
__device__ float d_gx[(size_t)2688 * NTB];          // [row][t*32+b]
__device__ float d_hs[(size_t)G_ * NTB];            // [g][t*32+b]
__device__ __align__(16) __half d_h16[2 * BG];      // ping-pong h fp16 [p][b][g]
__device__ float d_ghp[(size_t)2 * 2688 * 32];      // partials [q][row][b]
__device__ unsigned d_fM[42 * 8];
__device__ unsigned d_fC[14 * 8];

// ---------------- fp32x2 helpers (GEMMs) -----------------------------------
__device__ __forceinline__ void fma2(ull& d, ull a, ull b) {
    asm("fma.rn.f32x2 %0, %1, %2, %0;" : "+l"(d) : "l"(a), "l"(b));
}
__device__ __forceinline__ ull pack2(float x, float y) {
    ull r; asm("mov.b64 %0,{%1,%2};" : "=l"(r) : "f"(x), "f"(y)); return r;
}
__device__ __forceinline__ float2 unpack2(ull v) {
    float2 r; asm("mov.b64 {%0,%1},%2;" : "=f"(r.x), "=f"(r.y) : "l"(v)); return r;
}
union UF4 { float4 f4; ulonglong2 u2; };

// ---------------- HMMA helpers ---------------------------------------------
__device__ __forceinline__ uint32_t smem_u32(const void* p) {
    uint32_t a;
    asm("{ .reg .u64 t; cvta.to.shared.u64 t, %1; cvt.u32.u64 %0, t; }" : "=r"(a) : "l"(p));
    return a;
}
#define LDSM4(r0, r1, r2, r3, addr) \
    asm volatile("ldmatrix.sync.aligned.m8n8.x4.shared.b16 {%0,%1,%2,%3}, [%4];" \
        : "=r"(r0), "=r"(r1), "=r"(r2), "=r"(r3) : "r"(addr))
#define MMA16816(d, a0, a1, a2, a3, b0, b1) \
    asm volatile("mma.sync.aligned.m16n8k16.row.col.f32.f16.f16.f32 " \
        "{%0,%1,%2,%3},{%4,%5,%6,%7},{%8,%9},{%0,%1,%2,%3};" \
        : "+f"((d)[0]), "+f"((d)[1]), "+f"((d)[2]), "+f"((d)[3]) \
        : "r"(a0), "r"(a1), "r"(a2), "r"(a3), "r"(b0), "r"(b1))

// ---------------- GEMM (unchanged, passing since R11) ----------------------
template<int MODE>
__global__ void __launch_bounds__(256) gemm_k(
    const float* __restrict__ A, const float* __restrict__ Bsrc,
    const float* __restrict__ bias, float* __restrict__ Out, int K)
{
    __shared__ float As[8][132];
    __shared__ float Bs[8][132];
    const int tid = threadIdx.x;
    const int n0 = blockIdx.x * 128, m0 = blockIdx.y * 128;
    const int tn = tid & 15, tm = tid >> 4;
    const int ldn = tid >> 1, ldk = (tid & 1) * 4;
    const int ldk2 = tid >> 5, ldn2 = (tid & 31) * 4;

    const float* arow = A + (size_t)(m0 + ldn) * K + ldk;
    const float* bcol = nullptr;
    if (MODE == 0) {
        int n = n0 + ldn;
        bcol = Bsrc + ((size_t)(n & 31) * T_ + (n >> 5)) * C_ + ldk;
    }
    ull c2[8][4];
#pragma unroll
    for (int i = 0; i < 8; i++)
#pragma unroll
        for (int q = 0; q < 4; q++) c2[i][q] = 0ull;

    for (int kb = 0; kb < K; kb += 8) {
        float4 av = *(const float4*)(arow + kb);
        As[ldk+0][ldn]=av.x; As[ldk+1][ldn]=av.y;
        As[ldk+2][ldn]=av.z; As[ldk+3][ldn]=av.w;
        if (MODE == 0) {
            float4 bv = *(const float4*)(bcol + kb);
            Bs[ldk+0][ldn]=bv.x; Bs[ldk+1][ldn]=bv.y;
            Bs[ldk+2][ldn]=bv.z; Bs[ldk+3][ldn]=bv.w;
        } else {
            float4 bv = *(const float4*)(d_hs + (size_t)(kb + ldk2) * NTB + n0 + ldn2);
            *(float4*)&Bs[ldk2][ldn2] = bv;
        }
        __syncthreads();
#pragma unroll
        for (int k = 0; k < 8; k++) {
            float4 a0 = *(const float4*)&As[k][tm*4];
            float4 a1 = *(const float4*)&As[k][64 + tm*4];
            UF4 b0, b1;
            b0.f4 = *(const float4*)&Bs[k][tn*4];
            b1.f4 = *(const float4*)&Bs[k][64 + tn*4];
            float aa[8] = {a0.x,a0.y,a0.z,a0.w,a1.x,a1.y,a1.z,a1.w};
#pragma unroll
            for (int i = 0; i < 8; i++) {
                ull a2 = pack2(aa[i], aa[i]);
                fma2(c2[i][0], a2, b0.u2.x);
                fma2(c2[i][1], a2, b0.u2.y);
                fma2(c2[i][2], a2, b1.u2.x);
                fma2(c2[i][3], a2, b1.u2.y);
            }
        }
        __syncthreads();
    }
    float c[8][8];
#pragma unroll
    for (int i = 0; i < 8; i++)
#pragma unroll
        for (int q = 0; q < 4; q++) {
            float2 v = unpack2(c2[i][q]);
            c[i][2*q] = v.x; c[i][2*q+1] = v.y;
        }
    if (MODE == 0) {
#pragma unroll
        for (int i = 0; i < 8; i++) {
            int m = m0 + (i < 4 ? tm*4 + i : 64 + tm*4 + i - 4);
            float bi = bias[m];
            float* orow = Out + (size_t)m * NTB + n0;
            *(float4*)(orow + tn*4)      = make_float4(c[i][0]+bi, c[i][1]+bi, c[i][2]+bi, c[i][3]+bi);
            *(float4*)(orow + 64 + tn*4) = make_float4(c[i][4]+bi, c[i][5]+bi, c[i][6]+bi, c[i][7]+bi);
        }
    } else {
        float bi[8];
#pragma unroll
        for (int i = 0; i < 8; i++)
            bi[i] = bias[m0 + (i < 4 ? tm*4 + i : 64 + tm*4 + i - 4)];
#pragma unroll
        for (int j = 0; j < 8; j++) {
            int n = n0 + (j < 4 ? tn*4 + j : 64 + tn*4 + j - 4);
            size_t base = ((size_t)(n & 31) * T_ + (n >> 5)) * H_ + m0;
            float4 lo, hi;
            lo.x = fmaxf(c[0][j]+bi[0], 0.f); lo.y = fmaxf(c[1][j]+bi[1], 0.f);
            lo.z = fmaxf(c[2][j]+bi[2], 0.f); lo.w = fmaxf(c[3][j]+bi[3], 0.f);
            hi.x = fmaxf(c[4][j]+bi[4], 0.f); hi.y = fmaxf(c[5][j]+bi[5], 0.f);
            hi.z = fmaxf(c[6][j]+bi[6], 0.f); hi.w = fmaxf(c[7][j]+bi[7], 0.f);
            *(float4*)(Out + base + tm*4) = lo;
            *(float4*)(Out + base + 64 + tm*4) = hi;
        }
    }
}

// ---------------- init: flags + h16[0] -------------------------------------
__global__ void init_k(const float* __restrict__ h0) {
    int e = (blockIdx.x * 256 + threadIdx.x) * 4;
    if (e < BG) {
#pragma unroll
        for (int i = 0; i < 4; i++) d_h16[e + i] = __float2half(h0[e + i]);
    }
    if (blockIdx.x == 0) {
        if (threadIdx.x < 42) d_fM[threadIdx.x * 8] = 0u;
        else if (threadIdx.x < 56) d_fC[(threadIdx.x - 42) * 8] = 0u;
    }
}

// ---------------- persistent scan: 42 HMMA CTAs + 14 combine CTAs ----------
// SMEM (MMA role): A fp16 [128][456] at 0 (116736B), B fp16 [32][456] at
// 116736 (29184B). total 145920B -> 1 CTA/SM.
__global__ void __launch_bounds__(256, 1) scan_k(
    const float* __restrict__ h0, const float* __restrict__ w_hh,
    const float* __restrict__ b_hh, float* __restrict__ Out)
{
    extern __shared__ char smc[];
    const int tid = threadIdx.x;
    const int bid = blockIdx.x;

    if (bid < 42) {
        // ================= MMA role =================
        const int m = bid >> 1, q = bid & 1;
        __half* Asm = (__half*)smc;
        __half* Bsm = (__half*)(smc + 116736);
        const int wid = tid >> 5, lane = tid & 31;

        // load weights fp16 (once, resident for all 1024 steps)
        for (int e = tid; e < 128 * 448; e += 256) {
            int r = e / 448, k = e - r * 448;
            Asm[r * ASTR + k] = __float2half(w_hh[(size_t)(m * 128 + r) * 896 + q * 448 + k]);
        }
        __syncthreads();

        // per-warp ldmatrix base addresses
        const uint32_t aBase = smem_u32(Asm) +
            (uint32_t)(((wid * 16 + (lane & 15)) * ASTR + (lane >> 4) * 8) * 2);
        const uint32_t bBase0 = smem_u32(Bsm) +
            (uint32_t)((((lane >> 4) * 8 + (lane & 7)) * ASTR + ((lane >> 3) & 1) * 8) * 2);
        const uint32_t bBase2 = bBase0 + 16 * ASTR * 2;

        float* gp = d_ghp + (size_t)q * 2688 * 32;
        float* gpw = gp + (size_t)(m * 128 + wid * 16 + (lane >> 2)) * 32 + (lane & 3) * 2;

        for (int t = 0; t < T_; t++) {
            if (tid < 14) {
                while (((volatile unsigned*)d_fC)[tid * 8] < (unsigned)t) { }
            }
            __syncthreads();
            __threadfence();
            // B copy: h16[t&1] rows [b][g] -> SMEM [n=32][k=448] pad 456
            const ull* hsrc = (const ull*)(d_h16 + (size_t)(t & 1) * BG);
            for (int i = tid; i < 3584; i += 256) {
                int n = i / 112, kq = i - n * 112;
                ull v = __ldcg(hsrc + (size_t)n * 224 + q * 112 + kq);
                *(ull*)(Bsm + n * ASTR + kq * 4) = v;
            }
            __syncthreads();

            float acc[4][4];
#pragma unroll
            for (int i = 0; i < 4; i++)
#pragma unroll
                for (int j2 = 0; j2 < 4; j2++) acc[i][j2] = 0.f;

#pragma unroll 4
            for (int kc = 0; kc < 28; kc++) {
                uint32_t ko = kc * 32;
                uint32_t a0, a1, a2, a3, b0, b1, b2, b3, e0, e1, e2, e3;
                LDSM4(a0, a1, a2, a3, aBase + ko);
                LDSM4(b0, b1, b2, b3, bBase0 + ko);
                LDSM4(e0, e1, e2, e3, bBase2 + ko);
                MMA16816(acc[0], a0, a1, a2, a3, b0, b1);
                MMA16816(acc[1], a0, a1, a2, a3, b2, b3);
                MMA16816(acc[2], a0, a1, a2, a3, e0, e1);
                MMA16816(acc[3], a0, a1, a2, a3, e2, e3);
            }
            // writeback partials: rows lane>>2 (+8), cols nt*8 + (lane&3)*2
#pragma unroll
            for (int nt = 0; nt < 4; nt++) {
                *(float2*)(gpw + nt * 8)          = make_float2(acc[nt][0], acc[nt][1]);
                *(float2*)(gpw + 8 * 32 + nt * 8) = make_float2(acc[nt][2], acc[nt][3]);
            }
            __syncthreads();
            if (tid == 0) {
                __threadfence();
                ((volatile unsigned*)d_fM)[bid * 8] = (unsigned)(t + 1);
            }
        }
    } else {
        // ================= combine role =================
        const int cb = bid - 42;
        const int b = tid & 31, jq = tid >> 5;
        const int jb = cb * 64 + jq * 8;
        float* smt = (float*)smc;                 // [64][33] transpose buffer
        float hprev[8];
#pragma unroll
        for (int i = 0; i < 8; i++) hprev[i] = h0[b * 896 + jb + i];
        float bhr[8], bhz[8], bhn[8];
#pragma unroll
        for (int i = 0; i < 8; i++) {
            bhr[i] = b_hh[jb + i]; bhz[i] = b_hh[896 + jb + i]; bhn[i] = b_hh[1792 + jb + i];
        }
        const int bo = tid >> 3, gs = (tid & 7) * 8;

        for (int t = 0; t < T_; t++) {
            const int tb = t * 32 + b;
            float xr[8], xz[8], xn[8];
#pragma unroll
            for (int i = 0; i < 8; i++) {
                xr[i] = __ldcs(d_gx + (size_t)(jb + i) * NTB + tb);
                xz[i] = __ldcs(d_gx + (size_t)(896 + jb + i) * NTB + tb);
                xn[i] = __ldcs(d_gx + (size_t)(1792 + jb + i) * NTB + tb);
            }
            if (tid < 42) {
                while (((volatile unsigned*)d_fM)[tid * 8] < (unsigned)(t + 1)) { }
            }
            __syncthreads();
            __threadfence();
#pragma unroll
            for (int i = 0; i < 8; i++) {
                int j = jb + i;
                float gr = __ldcg(d_ghp + (size_t)j * 32 + b)
                         + __ldcg(d_ghp + (size_t)(2688 + j) * 32 + b) + bhr[i];
                float gz = __ldcg(d_ghp + (size_t)(896 + j) * 32 + b)
                         + __ldcg(d_ghp + (size_t)(2688 + 896 + j) * 32 + b) + bhz[i];
                float gn = __ldcg(d_ghp + (size_t)(1792 + j) * 32 + b)
                         + __ldcg(d_ghp + (size_t)(2688 + 1792 + j) * 32 + b) + bhn[i];
                float r = 1.f / (1.f + expf(-(xr[i] + gr)));
                float z = 1.f / (1.f + expf(-(xz[i] + gz)));
                float nn = tanhf(xn[i] + r * gn);
                float hn = (1.f - z) * nn + z * hprev[i];
                hprev[i] = hn;
                __stcs(d_hs + (size_t)j * NTB + tb, hn);
                smt[(jq * 8 + i) * 33 + b] = hn;
                if (t == T_ - 1) Out[(size_t)BTH + b * 896 + j] = hn;
            }
            __syncthreads();
            {   // coalesced fp16 write of next h (transposed via SMEM)
                __half hv[8];
#pragma unroll
                for (int i = 0; i < 8; i++) hv[i] = __float2half(smt[(gs + i) * 33 + bo]);
                *(uint4*)(d_h16 + (size_t)((t + 1) & 1) * BG + bo * 896 + cb * 64 + gs) = *(uint4*)hv;
            }
            __syncthreads();
            if (tid == 0) {
                __threadfence();
                ((volatile unsigned*)d_fC)[cb * 8] = (unsigned)(t + 1);
            }
        }
    }
}

// ---------------- launch ----------------------------------------------------
extern "C" void kernel_launch(void* const* d_in, const int* in_sizes, int n_in,
                              void* d_out, int out_size) {
    (void)in_sizes; (void)n_in; (void)out_size;
    const float* x      = (const float*)d_in[0];
    const float* state  = (const float*)d_in[1];
    const float* w_ih   = (const float*)d_in[2];
    const float* w_hh   = (const float*)d_in[3];
    const float* b_ih   = (const float*)d_in[4];
    const float* b_hh   = (const float*)d_in[5];
    const float* w_post = (const float*)d_in[6];
    const float* b_post = (const float*)d_in[7];
    float* out = (float*)d_out;

    float* gx = nullptr;
    cudaGetSymbolAddress((void**)&gx, d_gx);

    static const int SMEM = 116736 + 29184;   // 145,920 B
    cudaFuncSetAttribute(scan_k, cudaFuncAttributeMaxDynamicSharedMemorySize, SMEM);

    gemm_k<0><<<dim3(256, 21), 256>>>(w_ih, x, b_ih, gx, 128);
    init_k<<<28, 256>>>(state);
    scan_k<<<56, 256, SMEM>>>(state, w_hh, b_hh, out);
    gemm_k<1><<<dim3(256, 7), 256>>>(w_post, nullptr, b_post, out, 896);
}

// round 16
// speedup vs baseline: 3.3061x; 2.0134x over previous
#include <cuda_runtime.h>
#include <cuda_fp16.h>
#include <cstdint>
#include <cstddef>

typedef unsigned long long ull;

#define B_   32
#define T_   1024
#define C_   128
#define G_   896
#define H_   896
#define NTB  32768
#define BG   28672
#define BTH  29360128
#define ASTR 904              /* padded fp16 row stride (halves): 1808B, 16B-phase shift */
#define NCTA 56

// ---------------- static device scratch ------------------------------------
__device__ float d_gx[(size_t)2688 * NTB];          // [row][t*32+b]
__device__ float d_hs[(size_t)G_ * NTB];            // [g][t*32+b]
__device__ __align__(16) __half d_h16[2 * BG];      // ping-pong h fp16 [p][b][g]
__device__ unsigned d_f[NCTA * 8];                  // per-CTA step flags (32B padded)

// ---------------- fp32x2 helpers (GEMMs) -----------------------------------
__device__ __forceinline__ void fma2(ull& d, ull a, ull b) {
    asm("fma.rn.f32x2 %0, %1, %2, %0;" : "+l"(d) : "l"(a), "l"(b));
}
__device__ __forceinline__ ull pack2(float x, float y) {
    ull r; asm("mov.b64 %0,{%1,%2};" : "=l"(r) : "f"(x), "f"(y)); return r;
}
__device__ __forceinline__ float2 unpack2(ull v) {
    float2 r; asm("mov.b64 {%0,%1},%2;" : "=f"(r.x), "=f"(r.y) : "l"(v)); return r;
}
union UF4 { float4 f4; ulonglong2 u2; };

// ---------------- HMMA helpers ---------------------------------------------
__device__ __forceinline__ uint32_t smem_u32(const void* p) {
    uint32_t a;
    asm("{ .reg .u64 t; cvta.to.shared.u64 t, %1; cvt.u32.u64 %0, t; }" : "=r"(a) : "l"(p));
    return a;
}
#define LDSM4(r0, r1, r2, r3, addr) \
    asm volatile("ldmatrix.sync.aligned.m8n8.x4.shared.b16 {%0,%1,%2,%3}, [%4];" \
        : "=r"(r0), "=r"(r1), "=r"(r2), "=r"(r3) : "r"(addr))
#define MMA16816(d, a0, a1, a2, a3, b0, b1) \
    asm volatile("mma.sync.aligned.m16n8k16.row.col.f32.f16.f16.f32 " \
        "{%0,%1,%2,%3},{%4,%5,%6,%7},{%8,%9},{%0,%1,%2,%3};" \
        : "+f"((d)[0]), "+f"((d)[1]), "+f"((d)[2]), "+f"((d)[3]) \
        : "r"(a0), "r"(a1), "r"(a2), "r"(a3), "r"(b0), "r"(b1))

// ---------------- GEMM (unchanged, passing since R11) ----------------------
template<int MODE>
__global__ void __launch_bounds__(256) gemm_k(
    const float* __restrict__ A, const float* __restrict__ Bsrc,
    const float* __restrict__ bias, float* __restrict__ Out, int K)
{
    __shared__ float As[8][132];
    __shared__ float Bs[8][132];
    const int tid = threadIdx.x;
    const int n0 = blockIdx.x * 128, m0 = blockIdx.y * 128;
    const int tn = tid & 15, tm = tid >> 4;
    const int ldn = tid >> 1, ldk = (tid & 1) * 4;
    const int ldk2 = tid >> 5, ldn2 = (tid & 31) * 4;

    const float* arow = A + (size_t)(m0 + ldn) * K + ldk;
    const float* bcol = nullptr;
    if (MODE == 0) {
        int n = n0 + ldn;
        bcol = Bsrc + ((size_t)(n & 31) * T_ + (n >> 5)) * C_ + ldk;
    }
    ull c2[8][4];
#pragma unroll
    for (int i = 0; i < 8; i++)
#pragma unroll
        for (int q = 0; q < 4; q++) c2[i][q] = 0ull;

    for (int kb = 0; kb < K; kb += 8) {
        float4 av = *(const float4*)(arow + kb);
        As[ldk+0][ldn]=av.x; As[ldk+1][ldn]=av.y;
        As[ldk+2][ldn]=av.z; As[ldk+3][ldn]=av.w;
        if (MODE == 0) {
            float4 bv = *(const float4*)(bcol + kb);
            Bs[ldk+0][ldn]=bv.x; Bs[ldk+1][ldn]=bv.y;
            Bs[ldk+2][ldn]=bv.z; Bs[ldk+3][ldn]=bv.w;
        } else {
            float4 bv = *(const float4*)(d_hs + (size_t)(kb + ldk2) * NTB + n0 + ldn2);
            *(float4*)&Bs[ldk2][ldn2] = bv;
        }
        __syncthreads();
#pragma unroll
        for (int k = 0; k < 8; k++) {
            float4 a0 = *(const float4*)&As[k][tm*4];
            float4 a1 = *(const float4*)&As[k][64 + tm*4];
            UF4 b0, b1;
            b0.f4 = *(const float4*)&Bs[k][tn*4];
            b1.f4 = *(const float4*)&Bs[k][64 + tn*4];
            float aa[8] = {a0.x,a0.y,a0.z,a0.w,a1.x,a1.y,a1.z,a1.w};
#pragma unroll
            for (int i = 0; i < 8; i++) {
                ull a2 = pack2(aa[i], aa[i]);
                fma2(c2[i][0], a2, b0.u2.x);
                fma2(c2[i][1], a2, b0.u2.y);
                fma2(c2[i][2], a2, b1.u2.x);
                fma2(c2[i][3], a2, b1.u2.y);
            }
        }
        __syncthreads();
    }
    float c[8][8];
#pragma unroll
    for (int i = 0; i < 8; i++)
#pragma unroll
        for (int q = 0; q < 4; q++) {
            float2 v = unpack2(c2[i][q]);
            c[i][2*q] = v.x; c[i][2*q+1] = v.y;
        }
    if (MODE == 0) {
#pragma unroll
        for (int i = 0; i < 8; i++) {
            int m = m0 + (i < 4 ? tm*4 + i : 64 + tm*4 + i - 4);
            float bi = bias[m];
            float* orow = Out + (size_t)m * NTB + n0;
            *(float4*)(orow + tn*4)      = make_float4(c[i][0]+bi, c[i][1]+bi, c[i][2]+bi, c[i][3]+bi);
            *(float4*)(orow + 64 + tn*4) = make_float4(c[i][4]+bi, c[i][5]+bi, c[i][6]+bi, c[i][7]+bi);
        }
    } else {
        float bi[8];
#pragma unroll
        for (int i = 0; i < 8; i++)
            bi[i] = bias[m0 + (i < 4 ? tm*4 + i : 64 + tm*4 + i - 4)];
#pragma unroll
        for (int j = 0; j < 8; j++) {
            int n = n0 + (j < 4 ? tn*4 + j : 64 + tn*4 + j - 4);
            size_t base = ((size_t)(n & 31) * T_ + (n >> 5)) * H_ + m0;
            float4 lo, hi;
            lo.x = fmaxf(c[0][j]+bi[0], 0.f); lo.y = fmaxf(c[1][j]+bi[1], 0.f);
            lo.z = fmaxf(c[2][j]+bi[2], 0.f); lo.w = fmaxf(c[3][j]+bi[3], 0.f);
            hi.x = fmaxf(c[4][j]+bi[4], 0.f); hi.y = fmaxf(c[5][j]+bi[5], 0.f);
            hi.z = fmaxf(c[6][j]+bi[6], 0.f); hi.w = fmaxf(c[7][j]+bi[7], 0.f);
            *(float4*)(Out + base + tm*4) = lo;
            *(float4*)(Out + base + 64 + tm*4) = hi;
        }
    }
}

// ---------------- init: flags + h16[0] -------------------------------------
__global__ void init_k(const float* __restrict__ h0) {
    int e = (blockIdx.x * 256 + threadIdx.x) * 4;
    if (e < BG) {
#pragma unroll
        for (int i = 0; i < 4; i++) d_h16[e + i] = __float2half(h0[e + i]);
    }
    if (blockIdx.x == 0 && threadIdx.x < NCTA) d_f[threadIdx.x * 8] = 0u;
}

// ---------------- fused persistent scan: 56 CTAs ---------------------------
// CTA owns 16 j (jb..jb+15), all 3 gates = 48 A-rows, full K=896.
// Warps: kq = wid>>1 (K quarter of 224), nh = wid&1 (batch half of 16).
// Per warp/step: 42 A-LDSM.x4 + 14 B-LDSM.x4 + 84 HMMA -> partials in red,
// cross-warp K-reduce, exact fp32 gate math, h broadcast via d_h16 ping-pong.
// SMEM: A 48x904 fp16 (86784B) | B 32x904 fp16 (57856B) | red 4x48x34 f32
//       (26112B) | hbuf 32x18 fp16 (1152B)  -> 171904B, 1 CTA/SM.
__global__ void __launch_bounds__(256, 1) scan_k(
    const float* __restrict__ h0, const float* __restrict__ w_hh,
    const float* __restrict__ b_hh, float* __restrict__ Out)
{
    extern __shared__ char smc[];
    __half* Asm = (__half*)smc;                       // 48*904
    __half* Bsm = (__half*)(smc + 86784);             // 32*904
    float*  red = (float*)(smc + 86784 + 57856);      // 4*48*34
    __half* hbf = (__half*)(smc + 86784 + 57856 + 26112); // 32*18

    const int tid = threadIdx.x;
    const int bid = blockIdx.x;
    const int lane = tid & 31, wid = tid >> 5;
    const int jb = bid * 16;

    // ---- load W_hh slice fp16 (once, resident all 1024 steps) ----
    for (int e = tid; e < 48 * 896; e += 256) {
        int row = e / 896, k = e - row * 896;         // row = gate*16 + jl
        int gate = row >> 4, jl = row & 15;
        Asm[row * ASTR + k] = __float2half(w_hh[(size_t)(gate * 896 + jb + jl) * 896 + k]);
    }
    __syncthreads();

    // ---- per-warp MMA addressing ----
    const int kq = wid >> 1, nh = wid & 1;
    const int kqb = kq * 224;                          // K range [kqb, kqb+224)
    const uint32_t uA = smem_u32(Asm), uB = smem_u32(Bsm);
    uint32_t aAddr[3];
#pragma unroll
    for (int mt = 0; mt < 3; mt++)
        aAddr[mt] = uA + (uint32_t)(((mt * 16 + (lane & 15)) * ASTR + kqb + (lane >> 4) * 8) * 2);
    const uint32_t bAddr = uB + (uint32_t)(((nh * 16 + (lane >> 4) * 8 + (lane & 7)) * ASTR
                                            + kqb + ((lane >> 3) & 1) * 8) * 2);

    // ---- per-thread combine mapping ----
    const int m0 = wid;                                // = tid>>5 in 0..7
    const int b  = lane;                               // batch
    const int j0 = jb + m0, j1 = jb + m0 + 8;
    const float bhr0 = b_hh[j0],        bhr1 = b_hh[j1];
    const float bhz0 = b_hh[896 + j0],  bhz1 = b_hh[896 + j1];
    const float bhn0 = b_hh[1792 + j0], bhn1 = b_hh[1792 + j1];
    float hp0 = h0[b * 896 + j0], hp1 = h0[b * 896 + j1];

    for (int t = 0; t < T_; t++) {
        const int tb = t * 32 + b;
        // prefetch gx (6 scattered DRAM loads, in flight during spin+copy)
        float xr0 = __ldcs(d_gx + (size_t)j0 * NTB + tb);
        float xr1 = __ldcs(d_gx + (size_t)j1 * NTB + tb);
        float xz0 = __ldcs(d_gx + (size_t)(896 + j0) * NTB + tb);
        float xz1 = __ldcs(d_gx + (size_t)(896 + j1) * NTB + tb);
        float xn0 = __ldcs(d_gx + (size_t)(1792 + j0) * NTB + tb);
        float xn1 = __ldcs(d_gx + (size_t)(1792 + j1) * NTB + tb);

        // ---- wait for all producers of h(t) ----
        if (tid < NCTA) {
            while (((volatile unsigned*)d_f)[tid * 8] < (unsigned)t) { }
        }
        __syncthreads();
        __threadfence();

        // ---- copy full h16[t&1] -> Bsm [32][904] (14 LDG.128/thread) ----
        {
            const uint4* src = (const uint4*)(d_h16 + (size_t)(t & 1) * BG);
#pragma unroll
            for (int r4 = 0; r4 < 14; r4++) {
                int i4 = tid + 256 * r4;
                int n = i4 / 112, k16 = i4 - n * 112;
                uint4 v = __ldcg(src + n * 112 + k16);
                *(uint4*)(Bsm + n * ASTR + k16 * 8) = v;
            }
        }
        __syncthreads();

        // ---- MMA: 48 x 32(nh-half 16) x 224 per warp ----
        float acc[3][2][4];
#pragma unroll
        for (int mt = 0; mt < 3; mt++)
#pragma unroll
            for (int n8 = 0; n8 < 2; n8++)
#pragma unroll
                for (int c = 0; c < 4; c++) acc[mt][n8][c] = 0.f;

#pragma unroll 2
        for (int kc = 0; kc < 14; kc++) {
            uint32_t ko = kc * 32;                     // 16 halves = 32 bytes
            uint32_t b0, b1, b2, b3;
            LDSM4(b0, b1, b2, b3, bAddr + ko);
#pragma unroll
            for (int mt = 0; mt < 3; mt++) {
                uint32_t a0, a1, a2, a3;
                LDSM4(a0, a1, a2, a3, aAddr[mt] + ko);
                MMA16816(acc[mt][0], a0, a1, a2, a3, b0, b1);
                MMA16816(acc[mt][1], a0, a1, a2, a3, b2, b3);
            }
        }

        // ---- write partials: red[kq][m(48)][n(32) pad34] ----
        {
            const int row = lane >> 2, col = (lane & 3) * 2;
#pragma unroll
            for (int mt = 0; mt < 3; mt++)
#pragma unroll
                for (int n8 = 0; n8 < 2; n8++) {
                    int m = mt * 16 + row;
                    int nn = nh * 16 + n8 * 8 + col;
                    float* p = red + (size_t)(kq * 48 + m) * 34 + nn;
                    *(float2*)p            = make_float2(acc[mt][n8][0], acc[mt][n8][1]);
                    *(float2*)(p + 8 * 34) = make_float2(acc[mt][n8][2], acc[mt][n8][3]);
                }
        }
        __syncthreads();

        // ---- K-reduce + gates (thread owns (j0,b),(j1,b) triples) ----
        float gh[6];
#pragma unroll
        for (int i = 0; i < 6; i++) {
            int m = m0 + 8 * i;
            float s = red[(size_t)(0 * 48 + m) * 34 + b]
                    + red[(size_t)(1 * 48 + m) * 34 + b]
                    + red[(size_t)(2 * 48 + m) * 34 + b]
                    + red[(size_t)(3 * 48 + m) * 34 + b];
            gh[i] = s;
        }
        float r0 = 1.f / (1.f + expf(-(xr0 + gh[0] + bhr0)));
        float r1 = 1.f / (1.f + expf(-(xr1 + gh[1] + bhr1)));
        float z0 = 1.f / (1.f + expf(-(xz0 + gh[2] + bhz0)));
        float z1 = 1.f / (1.f + expf(-(xz1 + gh[3] + bhz1)));
        float n0v = tanhf(xn0 + r0 * (gh[4] + bhn0));
        float n1v = tanhf(xn1 + r1 * (gh[5] + bhn1));
        float hn0 = (1.f - z0) * n0v + z0 * hp0;
        float hn1 = (1.f - z1) * n1v + z1 * hp1;
        hp0 = hn0; hp1 = hn1;

        __stcs(d_hs + (size_t)j0 * NTB + tb, hn0);
        __stcs(d_hs + (size_t)j1 * NTB + tb, hn1);
        hbf[b * 18 + m0]     = __float2half(hn0);
        hbf[b * 18 + m0 + 8] = __float2half(hn1);

        if (t == T_ - 1) {
            Out[(size_t)BTH + b * 896 + j0] = hn0;
            Out[(size_t)BTH + b * 896 + j1] = hn1;
            break;
        }
        __syncthreads();

        // ---- coalesced h16 chunk writeback + flag ----
        {
            int b2 = tid >> 3, jp = tid & 7;
            uint32_t v = *(uint32_t*)(hbf + b2 * 18 + 2 * jp);
            *(uint32_t*)(d_h16 + (size_t)((t + 1) & 1) * BG + b2 * 896 + jb + 2 * jp) = v;
        }
        __threadfence();
        __syncthreads();
        if (tid == 0)
            ((volatile unsigned*)d_f)[bid * 8] = (unsigned)(t + 1);
    }
}

// ---------------- launch ----------------------------------------------------
extern "C" void kernel_launch(void* const* d_in, const int* in_sizes, int n_in,
                              void* d_out, int out_size) {
    (void)in_sizes; (void)n_in; (void)out_size;
    const float* x      = (const float*)d_in[0];
    const float* state  = (const float*)d_in[1];
    const float* w_ih   = (const float*)d_in[2];
    const float* w_hh   = (const float*)d_in[3];
    const float* b_ih   = (const float*)d_in[4];
    const float* b_hh   = (const float*)d_in[5];
    const float* w_post = (const float*)d_in[6];
    const float* b_post = (const float*)d_in[7];
    float* out = (float*)d_out;

    float* gx = nullptr;
    cudaGetSymbolAddress((void**)&gx, d_gx);

    static const int SMEM = 86784 + 57856 + 26112 + 1152;   // 171,904 B
    cudaFuncSetAttribute(scan_k, cudaFuncAttributeMaxDynamicSharedMemorySize, SMEM);

    gemm_k<0><<<dim3(256, 21), 256>>>(w_ih, x, b_ih, gx, 128);
    init_k<<<28, 256>>>(state);
    scan_k<<<NCTA, 256, SMEM>>>(state, w_hh, b_hh, out);
    gemm_k<1><<<dim3(256, 7), 256>>>(w_post, nullptr, b_post, out, 896);
}